// round 14
// baseline (speedup 1.0000x reference)
#include <cuda_runtime.h>
#include <cuda_fp16.h>
#include <mma.h>
#include <cstdint>

#define NN 100000
#define EE 1600000
#define FT 96
#define TT 12
#define NB 391  // ceil(NN/256)

typedef unsigned long long u64;
using namespace nvcuda;

// ---------------- scratch (device globals; no runtime allocation) ----------------
__device__ float g_wx[(size_t)NN * FT];
__device__ float g_agg[(size_t)NN * FT];
__device__ float g_dis[NN];
__device__ float g_wdeg[NN];
__device__ int   g_cnt[NN];
__device__ int   g_off[NN + 1];
__device__ int   g_cur[NN];
__device__ int   g_bsum[NB];
__device__ int   g_bpre[NB];
__device__ u64   g_sSN[EE];
__device__ float g_M[3 * 8 * 32];
__device__ float g_gb[3 * 32];
__device__ float g_probs[TT];

__device__ __forceinline__ float sigf(float x) { return 1.0f / (1.0f + __expf(-x)); }
__device__ __forceinline__ float tanhfast(float x) {
    return __fmaf_rn(2.0f, 1.0f / (1.0f + __expf(-2.0f * x)), -1.0f);
}

// pack 8 floats -> hi fp16 uint4 and lo (residual) fp16 uint4
__device__ __forceinline__ void hilo8(const float* v, uint4& hi, uint4& lo) {
    __half h[8];
    float r[8];
#pragma unroll
    for (int i = 0; i < 8; i++) { h[i] = __float2half_rn(v[i]); r[i] = v[i] - __half2float(h[i]); }
    __half2 a0 = __halves2half2(h[0], h[1]), a1 = __halves2half2(h[2], h[3]);
    __half2 a2 = __halves2half2(h[4], h[5]), a3 = __halves2half2(h[6], h[7]);
    hi.x = *(uint32_t*)&a0; hi.y = *(uint32_t*)&a1; hi.z = *(uint32_t*)&a2; hi.w = *(uint32_t*)&a3;
    __half2 b0 = __floats2half2_rn(r[0], r[1]), b1 = __floats2half2_rn(r[2], r[3]);
    __half2 b2 = __floats2half2_rn(r[4], r[5]), b3 = __floats2half2_rn(r[6], r[7]);
    lo.x = *(uint32_t*)&b0; lo.y = *(uint32_t*)&b1; lo.z = *(uint32_t*)&b2; lo.w = *(uint32_t*)&b3;
}

// ---------------- front-end kernels: exact R9 versions ----------------
__global__ void k_precompute(const float* czw, const float* czb, const float* lzw, const float* lzb,
                             const float* crw, const float* crb, const float* lrw, const float* lrb,
                             const float* chw, const float* chb, const float* lhw, const float* lhb,
                             const float* att)
{
    int tid = threadIdx.x;
    int f = tid >> 5, l = tid & 31;
#pragma unroll
    for (int g = 0; g < 3; g++) {
        const float* CW = (g == 0) ? czw : (g == 1) ? crw : chw;
        const float* CB = (g == 0) ? czb : (g == 1) ? crb : chb;
        const float* LW = (g == 0) ? lzw : (g == 1) ? lrw : lhw;
        const float* LB = (g == 0) ? lzb : (g == 1) ? lrb : lhb;
        float m = 0.f;
        for (int k = 0; k < 32; k++) m += CW[f * 32 + k] * LW[k * 32 + l];
        g_M[g * 256 + f * 32 + l] = m;
        if (f == 0) {
            float b = LB[l];
            for (int k = 0; k < 32; k++) b += CB[k] * LW[k * 32 + l];
            g_gb[g * 32 + l] = b;
        }
    }
    if (tid < TT) {
        float mx = -1e30f;
        for (int t = 0; t < TT; t++) mx = fmaxf(mx, att[t]);
        float s = 0.f;
        for (int t = 0; t < TT; t++) s += __expf(att[t] - mx);
        g_probs[tid] = __expf(att[tid] - mx) / s;
    }
}

__global__ void k_wx(const float* __restrict__ x, const float* __restrict__ mlp_w,
                     const float* __restrict__ mlp_b)
{
    __shared__ float sW[TT * FT];
    __shared__ float sB[TT];
    int tid = threadIdx.x;
    for (int i = tid; i < TT * FT; i += 256) {
        int t = i / FT, j = i % FT;
        sW[i] = mlp_w[j * TT + t];
    }
    if (tid < TT) sB[tid] = mlp_b[tid];
    __syncthreads();

    int n = blockIdx.x * 8 + (tid >> 5);
    if (n >= NN) return;
    int lane = tid & 31;
    const float* xr = x + (size_t)n * FT;
    float x0 = xr[lane], x1 = xr[lane + 32], x2 = xr[lane + 64];

    float p[TT];
#pragma unroll
    for (int t = 0; t < TT; t++)
        p[t] = x0 * sW[t * FT + lane] + x1 * sW[t * FT + lane + 32] + x2 * sW[t * FT + lane + 64];
#pragma unroll
    for (int off = 16; off; off >>= 1) {
#pragma unroll
        for (int t = 0; t < TT; t++) p[t] += __shfl_xor_sync(0xffffffffu, p[t], off);
    }
    float* wr = g_wx + (size_t)n * FT;
    int j0 = lane % 12, j1 = (lane + 32) % 12, j2 = (lane + 64) % 12;
    wr[lane]      = x0 * sigf(p[j0] + sB[j0]);
    wr[lane + 32] = x1 * sigf(p[j1] + sB[j1]);
    wr[lane + 64] = x2 * sigf(p[j2] + sB[j2]);
    if (lane == 0) { g_cnt[n] = 0; g_wdeg[n] = 0.f; }
}

__global__ void k_hist(const int* __restrict__ ei, const float* __restrict__ ew)
{
    int e = blockIdx.x * 256 + threadIdx.x;
    if (e < EE) {
        int d = ei[EE + e];
        atomicAdd(&g_cnt[d], 1);
        atomicAdd(&g_wdeg[d], ew[e]);
    }
}

__global__ void k_scan1()
{
    __shared__ int s[256];
    int t = threadIdx.x;
    int n = blockIdx.x * 256 + t;
    int v = (n < NN) ? g_cnt[n] : 0;
    s[t] = v; __syncthreads();
#pragma unroll
    for (int o = 128; o; o >>= 1) {
        if (t < o) s[t] += s[t + o];
        __syncthreads();
    }
    if (t == 0) g_bsum[blockIdx.x] = s[0];
}

__global__ void k_scan2()
{
    __shared__ int s[512];
    int t = threadIdx.x;
    int v = (t < NB) ? g_bsum[t] : 0;
    s[t] = v; __syncthreads();
#pragma unroll
    for (int o = 1; o < 512; o <<= 1) {
        int x = (t >= o) ? s[t - o] : 0;
        __syncthreads();
        s[t] += x;
        __syncthreads();
    }
    if (t < NB) g_bpre[t] = s[t] - v;
}

__global__ void k_scan3()
{
    __shared__ int s[256];
    int t = threadIdx.x;
    int n = blockIdx.x * 256 + t;
    int v = (n < NN) ? g_cnt[n] : 0;
    s[t] = v; __syncthreads();
#pragma unroll
    for (int o = 1; o < 256; o <<= 1) {
        int x = (t >= o) ? s[t - o] : 0;
        __syncthreads();
        s[t] += x;
        __syncthreads();
    }
    if (n < NN) {
        int off = g_bpre[blockIdx.x] + s[t] - v;
        g_off[n] = off;
        g_cur[n] = off;
        g_dis[n] = rsqrtf(g_wdeg[n] + 1.0f);
    }
    if (n == 0) g_off[NN] = EE;
}

__global__ void k_scatter(const int* __restrict__ ei, const float* __restrict__ ew)
{
    int e = blockIdx.x * 256 + threadIdx.x;
    if (e >= EE) return;
    int s = ei[e], d = ei[EE + e];
    float nm = g_dis[s] * ew[e] * g_dis[d];
    int p = atomicAdd(&g_cur[d], 1);
    g_sSN[p] = ((u64)(unsigned)s) | ((u64)__float_as_uint(nm) << 32);
}

__global__ void k_gather()
{
    int n = blockIdx.x * 8 + (threadIdx.x >> 5);
    if (n >= NN) return;
    int lane = threadIdx.x & 31;
    int beg = g_off[n], end = g_off[n + 1];
    float ds = g_dis[n];
    float nmself = ds * ds;
    const float* wn = g_wx + (size_t)n * FT;
    float a0 = nmself * wn[lane];
    float a1 = nmself * wn[lane + 32];
    float a2 = nmself * wn[lane + 64];

    for (int b = beg; b < end; b += 32) {
        int m = end - b; if (m > 32) m = 32;
        u64 v = (b + lane < end) ? g_sSN[b + lane] : 0ull;
        unsigned vlo = (unsigned)(v & 0xffffffffu);
        unsigned vhi = (unsigned)(v >> 32);
#pragma unroll 4
        for (int i = 0; i < m; i++) {
            int s = (int)__shfl_sync(0xffffffffu, vlo, i);
            float nm = __uint_as_float(__shfl_sync(0xffffffffu, vhi, i));
            const float* wr = g_wx + (size_t)s * FT;
            a0 += nm * wr[lane];
            a1 += nm * wr[lane + 32];
            a2 += nm * wr[lane + 64];
        }
    }
    float* ar = g_agg + (size_t)n * FT;
    ar[lane] = a0; ar[lane + 32] = a1; ar[lane + 64] = a2;
}

// ================= wmma tensor-core GRU: 128 nodes/CTA, fp16 triple-split =================
#define LDA   136   // A tile ld (halves); pad -> conflict-free LDSM
#define LDB1  72
#define LDB2  40
#define LDD   128   // D stored col-major [c][r]
#define LDAGG 97

#define OF_A    0                         // 128*136*2 = 34816
#define OF_B1   34816                     // 128*72*2  = 18432
#define OF_B2   53248                     // 128*40*2  = 10240
#define OF_D    63488                     // 64*128*4  = 32768
#define OF_AGG  96256                     // 128*97*4  = 49664
#define OF_MISC 145920                    // 504 floats = 2016
#define SMEM_TC 147968

__global__ void __launch_bounds__(128) k_gru_wmma(
    const float* __restrict__ lzw, const float* __restrict__ lrw,
    const float* __restrict__ lhw, const float* __restrict__ out_w,
    const float* __restrict__ out_b, float* __restrict__ out)
{
    extern __shared__ char dsm[];
    __half* sA  = (__half*)(dsm + OF_A);
    __half* sB1 = (__half*)(dsm + OF_B1);
    __half* sB2 = (__half*)(dsm + OF_B2);
    float* sD   = (float*)(dsm + OF_D);
    float* sAgg = (float*)(dsm + OF_AGG);
    float* sBias = (float*)(dsm + OF_MISC);  // 96
    float* sP    = sBias + 96;               // 12
    float* sOb   = sP + 12;                  // 12
    float* sOw   = sOb + 12;                 // 384

    int tid = threadIdx.x;  // 128
    int w = tid >> 5;
    int base = blockIdx.x * 128;

    if (tid < 96) sBias[tid] = g_gb[tid];
    if (tid < TT) { sP[tid] = g_probs[tid]; sOb[tid] = out_b[tid]; }
    for (int i = tid; i < 32 * TT; i += 128) sOw[i] = out_w[i];

    // stage agg tile (coalesced); OOB rows -> 0
    for (int i = tid; i < 128 * FT; i += 128) {
        int r = i / FT, j = i % FT;
        int gn = base + r;
        sAgg[r * LDAGG + j] = (gn < NN) ? g_agg[(size_t)gn * FT + j] : 0.f;
    }

    // build B1/B2: thread = K-cat row k. rows 0-39: W_hi, 40-79: W_hi, 80-119: W_lo, 120-127: 0
    {
        int k = tid;
        int ks = (k < 40) ? k : ((k < 80) ? k - 40 : ((k < 120) ? k - 80 : -1));
        bool hipart = k < 80;
        for (int n = 0; n < 64; n++) {
            float wv = 0.f;
            if (ks >= 0) {
                int c = n & 31;
                if (n < 32) wv = (ks < 8) ? g_M[ks * 32 + c] : lzw[1024 + (ks - 8) * 32 + c];
                else        wv = (ks < 8) ? g_M[256 + ks * 32 + c] : lrw[1024 + (ks - 8) * 32 + c];
            }
            __half hh = __float2half_rn(wv);
            sB1[k * LDB1 + n] = hipart ? hh : __float2half_rn(wv - __half2float(hh));
        }
        for (int n = 0; n < 32; n++) {
            float wv = 0.f;
            if (ks >= 0) wv = (ks < 8) ? g_M[512 + ks * 32 + n] : lhw[1024 + (ks - 8) * 32 + n];
            __half hh = __float2half_rn(wv);
            sB2[k * LDB2 + n] = hipart ? hh : __float2half_rn(wv - __half2float(hh));
        }
    }

    // zero H slots + pad cols of own A row (16B-aligned chunks)
    {
        uint4 z4 = make_uint4(0, 0, 0, 0);
        __half* row = sA + tid * LDA;
#pragma unroll
        for (int g = 0; g < 4; g++) {
            *(uint4*)(row + 8 + g * 8)  = z4;
            *(uint4*)(row + 48 + g * 8) = z4;
            *(uint4*)(row + 88 + g * 8) = z4;
        }
        *(uint4*)(row + 120) = z4;
    }
    __syncthreads();

    float H[32], Ha[32], zz[32];
#pragma unroll
    for (int j = 0; j < 32; j++) { H[j] = 0.f; Ha[j] = 0.f; }

    const float* aRow = sAgg + tid * LDAGG;
    __half* myrow = sA + tid * LDA;

#pragma unroll 1
    for (int t = 0; t < TT; t++) {
        // ---- write agg slice (hi @0, lo @40, hi @80) ----
        {
            float av[8];
#pragma unroll
            for (int f = 0; f < 8; f++) av[f] = aRow[f * TT + t];
            uint4 hi4, lo4;
            hilo8(av, hi4, lo4);
            *(uint4*)(myrow + 0)  = hi4;
            *(uint4*)(myrow + 40) = lo4;
            *(uint4*)(myrow + 80) = hi4;
        }
        __syncthreads();

        // ---- MMA1: A[128x128] @ B1[128x64] -> D cols 0..63 (col-major) ----
#pragma unroll
        for (int mi = 0; mi < 2; mi++) {
            int m = w * 2 + mi;
#pragma unroll
            for (int n = 0; n < 4; n++) {
                wmma::fragment<wmma::accumulator, 16, 16, 16, float> acc;
                wmma::fill_fragment(acc, 0.f);
#pragma unroll
                for (int k = 0; k < 8; k++) {
                    wmma::fragment<wmma::matrix_a, 16, 16, 16, __half, wmma::row_major> af;
                    wmma::fragment<wmma::matrix_b, 16, 16, 16, __half, wmma::row_major> bf;
                    wmma::load_matrix_sync(af, sA + (m * 16) * LDA + k * 16, LDA);
                    wmma::load_matrix_sync(bf, sB1 + (k * 16) * LDB1 + n * 16, LDB1);
                    wmma::mma_sync(acc, af, bf, acc);
                }
                wmma::store_matrix_sync(sD + (n * 16) * LDD + m * 16, acc, LDD, wmma::mem_col_major);
            }
        }
        __syncthreads();

        // ---- act-zr: z gates + H*R; write H*R into H slots ----
        {
            float hr[32];
#pragma unroll
            for (int c = 0; c < 32; c++) {
                zz[c] = sigf(sD[c * LDD + tid] + sBias[c]);
                hr[c] = sigf(sD[(32 + c) * LDD + tid] + sBias[32 + c]) * H[c];
            }
#pragma unroll
            for (int g = 0; g < 4; g++) {
                uint4 hh, hl;
                hilo8(hr + g * 8, hh, hl);
                *(uint4*)(myrow + 8 + g * 8)  = hh;
                *(uint4*)(myrow + 48 + g * 8) = hl;
                *(uint4*)(myrow + 88 + g * 8) = hh;
            }
        }
        __syncthreads();

        // ---- MMA2: A[128x128] @ B2[128x32] -> D cols 0..31 ----
#pragma unroll
        for (int mi = 0; mi < 2; mi++) {
            int m = w * 2 + mi;
#pragma unroll
            for (int n = 0; n < 2; n++) {
                wmma::fragment<wmma::accumulator, 16, 16, 16, float> acc;
                wmma::fill_fragment(acc, 0.f);
#pragma unroll
                for (int k = 0; k < 8; k++) {
                    wmma::fragment<wmma::matrix_a, 16, 16, 16, __half, wmma::row_major> af;
                    wmma::fragment<wmma::matrix_b, 16, 16, 16, __half, wmma::row_major> bf;
                    wmma::load_matrix_sync(af, sA + (m * 16) * LDA + k * 16, LDA);
                    wmma::load_matrix_sync(bf, sB2 + (k * 16) * LDB2 + n * 16, LDB2);
                    wmma::mma_sync(acc, af, bf, acc);
                }
                wmma::store_matrix_sync(sD + (n * 16) * LDD + m * 16, acc, LDD, wmma::mem_col_major);
            }
        }
        __syncthreads();

        // ---- act-h: candidate, H update, accumulate; write new H into H slots ----
        {
            float pt = sP[t];
#pragma unroll
            for (int c = 0; c < 32; c++) {
                float ht = tanhfast(sD[c * LDD + tid] + sBias[64 + c]);
                H[c] = zz[c] * H[c] + (1.0f - zz[c]) * ht;
                Ha[c] += pt * H[c];
            }
#pragma unroll
            for (int g = 0; g < 4; g++) {
                uint4 hh, hl;
                hilo8(H + g * 8, hh, hl);
                *(uint4*)(myrow + 8 + g * 8)  = hh;
                *(uint4*)(myrow + 48 + g * 8) = hl;
                *(uint4*)(myrow + 88 + g * 8) = hh;
            }
        }
        // loop-top __syncthreads orders these writes (and sD reads) vs next MMA1
    }

    // ---- output head: relu(Ha) @ out_w + out_b ----
#pragma unroll
    for (int j = 0; j < 32; j++) Ha[j] = fmaxf(Ha[j], 0.f);
    float o[TT];
#pragma unroll
    for (int c = 0; c < TT; c++) {
        float acc = sOb[c];
#pragma unroll
        for (int j = 0; j < 32; j++) acc += Ha[j] * sOw[j * TT + c];
        o[c] = acc;
    }
    __syncthreads();  // done with sD
    float* sOut = sD;
#pragma unroll
    for (int c = 0; c < TT; c++) sOut[tid * 13 + c] = o[c];
    __syncthreads();
    for (int i = tid; i < 128 * TT; i += 128) {
        int r = i / TT, c = i % TT;
        int gn = base + r;
        if (gn < NN) out[(size_t)gn * TT + c] = sOut[r * 13 + c];
    }
}

// ---------------- launch ----------------
extern "C" void kernel_launch(void* const* d_in, const int* in_sizes, int n_in,
                              void* d_out, int out_size)
{
    const float* x     = (const float*)d_in[0];
    const int*   ei    = (const int*)d_in[1];
    const float* ew    = (const float*)d_in[2];
    const float* mlp_w = (const float*)d_in[3];
    const float* mlp_b = (const float*)d_in[4];
    const float* att   = (const float*)d_in[5];
    const float* czw   = (const float*)d_in[6];
    const float* czb   = (const float*)d_in[7];
    const float* lzw   = (const float*)d_in[8];
    const float* lzb   = (const float*)d_in[9];
    const float* crw   = (const float*)d_in[10];
    const float* crb   = (const float*)d_in[11];
    const float* lrw   = (const float*)d_in[12];
    const float* lrb   = (const float*)d_in[13];
    const float* chw   = (const float*)d_in[14];
    const float* chb   = (const float*)d_in[15];
    const float* lhw   = (const float*)d_in[16];
    const float* lhb   = (const float*)d_in[17];
    const float* ow    = (const float*)d_in[18];
    const float* ob    = (const float*)d_in[19];
    float* out = (float*)d_out;

    cudaFuncSetAttribute(k_gru_wmma, cudaFuncAttributeMaxDynamicSharedMemorySize, SMEM_TC);

    k_precompute<<<1, 256>>>(czw, czb, lzw, lzb, crw, crb, lrw, lrb, chw, chb, lhw, lhb, att);
    k_wx<<<(NN + 7) / 8, 256>>>(x, mlp_w, mlp_b);
    k_hist<<<(EE + 255) / 256, 256>>>(ei, ew);
    k_scan1<<<NB, 256>>>();
    k_scan2<<<1, 512>>>();
    k_scan3<<<NB, 256>>>();
    k_scatter<<<(EE + 255) / 256, 256>>>(ei, ew);
    k_gather<<<(NN + 7) / 8, 256>>>();
    k_gru_wmma<<<(NN + 127) / 128, 128, SMEM_TC>>>(lzw, lrw, lhw, ow, ob, out);
}

// round 15
// speedup vs baseline: 1.3063x; 1.3063x over previous
#include <cuda_runtime.h>

#define NN 100000
#define EE 1600000
#define FT 96
#define TT 12
#define NB 391  // ceil(NN/256)

typedef unsigned long long u64;

// ---------------- scratch (device globals; no runtime allocation) ----------------
__device__ float g_wx[(size_t)NN * FT];   // weighted features, node-major [n][j]
__device__ float g_dis[NN];
__device__ float g_wdeg[NN];
__device__ int   g_cnt[NN];
__device__ int   g_off[NN + 1];
__device__ int   g_cur[NN];
__device__ int   g_bsum[NB];
__device__ int   g_bpre[NB];
__device__ u64   g_sSN[EE];               // packed (src, norm) bucketed by dst
__device__ float g_M[3 * 8 * 32];
__device__ float g_gb[3 * 32];
__device__ float g_probs[TT];

__device__ __forceinline__ float sigf(float x) { return 1.0f / (1.0f + __expf(-x)); }

// ---------------- fused weight precompute + softmax(att) ----------------
__global__ void k_precompute(const float* czw, const float* czb, const float* lzw, const float* lzb,
                             const float* crw, const float* crb, const float* lrw, const float* lrb,
                             const float* chw, const float* chb, const float* lhw, const float* lhb,
                             const float* att)
{
    int tid = threadIdx.x;           // 256
    int f = tid >> 5, l = tid & 31;
#pragma unroll
    for (int g = 0; g < 3; g++) {
        const float* CW = (g == 0) ? czw : (g == 1) ? crw : chw;
        const float* CB = (g == 0) ? czb : (g == 1) ? crb : chb;
        const float* LW = (g == 0) ? lzw : (g == 1) ? lrw : lhw;
        const float* LB = (g == 0) ? lzb : (g == 1) ? lrb : lhb;
        float m = 0.f;
        for (int k = 0; k < 32; k++) m += CW[f * 32 + k] * LW[k * 32 + l];
        g_M[g * 256 + f * 32 + l] = m;
        if (f == 0) {
            float b = LB[l];
            for (int k = 0; k < 32; k++) b += CB[k] * LW[k * 32 + l];
            g_gb[g * 32 + l] = b;
        }
    }
    if (tid < TT) {
        float mx = -1e30f;
        for (int t = 0; t < TT; t++) mx = fmaxf(mx, att[t]);
        float s = 0.f;
        for (int t = 0; t < TT; t++) s += __expf(att[t] - mx);
        g_probs[tid] = __expf(att[tid] - mx) / s;
    }
}

// ---------------- wx = x * sigmoid(x_flat @ mlp_w + mlp_b); reset cnt/wdeg ----------------
__global__ void k_wx(const float* __restrict__ x, const float* __restrict__ mlp_w,
                     const float* __restrict__ mlp_b)
{
    __shared__ float sW[TT * FT];  // transposed: [t][j]
    __shared__ float sB[TT];
    int tid = threadIdx.x;  // 256
    for (int i = tid; i < TT * FT; i += 256) {
        int t = i / FT, j = i % FT;
        sW[i] = mlp_w[j * TT + t];
    }
    if (tid < TT) sB[tid] = mlp_b[tid];
    __syncthreads();

    int n = blockIdx.x * 8 + (tid >> 5);
    if (n >= NN) return;
    int lane = tid & 31;
    const float* xr = x + (size_t)n * FT;
    float x0 = xr[lane], x1 = xr[lane + 32], x2 = xr[lane + 64];

    float p[TT];
#pragma unroll
    for (int t = 0; t < TT; t++)
        p[t] = x0 * sW[t * FT + lane] + x1 * sW[t * FT + lane + 32] + x2 * sW[t * FT + lane + 64];
#pragma unroll
    for (int off = 16; off; off >>= 1) {
#pragma unroll
        for (int t = 0; t < TT; t++) p[t] += __shfl_xor_sync(0xffffffffu, p[t], off);
    }
    float* wr = g_wx + (size_t)n * FT;
    int j0 = lane % 12, j1 = (lane + 32) % 12, j2 = (lane + 64) % 12;
    wr[lane]      = x0 * sigf(p[j0] + sB[j0]);
    wr[lane + 32] = x1 * sigf(p[j1] + sB[j1]);
    wr[lane + 64] = x2 * sigf(p[j2] + sB[j2]);
    if (lane == 0) { g_cnt[n] = 0; g_wdeg[n] = 0.f; }  // replay-safe reset
}

// ---------------- histogram: in-edge count + weighted degree ----------------
__global__ void k_hist(const int* __restrict__ ei, const float* __restrict__ ew)
{
    int e = blockIdx.x * 256 + threadIdx.x;
    if (e < EE) {
        int d = ei[EE + e];
        atomicAdd(&g_cnt[d], 1);
        atomicAdd(&g_wdeg[d], ew[e]);
    }
}

// ---------------- scan stage 1 ----------------
__global__ void k_scan1()
{
    __shared__ int s[256];
    int t = threadIdx.x;
    int n = blockIdx.x * 256 + t;
    int v = (n < NN) ? g_cnt[n] : 0;
    s[t] = v; __syncthreads();
#pragma unroll
    for (int o = 128; o; o >>= 1) {
        if (t < o) s[t] += s[t + o];
        __syncthreads();
    }
    if (t == 0) g_bsum[blockIdx.x] = s[0];
}

// ---------------- scan stage 2 ----------------
__global__ void k_scan2()
{
    __shared__ int s[512];
    int t = threadIdx.x;  // 512
    int v = (t < NB) ? g_bsum[t] : 0;
    s[t] = v; __syncthreads();
#pragma unroll
    for (int o = 1; o < 512; o <<= 1) {
        int x = (t >= o) ? s[t - o] : 0;
        __syncthreads();
        s[t] += x;
        __syncthreads();
    }
    if (t < NB) g_bpre[t] = s[t] - v;
}

// ---------------- scan stage 3 ----------------
__global__ void k_scan3()
{
    __shared__ int s[256];
    int t = threadIdx.x;
    int n = blockIdx.x * 256 + t;
    int v = (n < NN) ? g_cnt[n] : 0;
    s[t] = v; __syncthreads();
#pragma unroll
    for (int o = 1; o < 256; o <<= 1) {
        int x = (t >= o) ? s[t - o] : 0;
        __syncthreads();
        s[t] += x;
        __syncthreads();
    }
    if (n < NN) {
        int off = g_bpre[blockIdx.x] + s[t] - v;
        g_off[n] = off;
        g_cur[n] = off;
        g_dis[n] = rsqrtf(g_wdeg[n] + 1.0f);
    }
    if (n == 0) g_off[NN] = EE;
}

// ---------------- scatter edges into dst-buckets ----------------
__global__ void k_scatter(const int* __restrict__ ei, const float* __restrict__ ew)
{
    int e = blockIdx.x * 256 + threadIdx.x;
    if (e >= EE) return;
    int s = ei[e], d = ei[EE + e];
    float nm = g_dis[s] * ew[e] * g_dis[d];
    int p = atomicAdd(&g_cur[d], 1);
    g_sSN[p] = ((u64)(unsigned)s) | ((u64)__float_as_uint(nm) << 32);
}

// ============ FUSED gather + GRU: 32 nodes per 128-thread block ============
// Phase 1: each warp gathers 8 nodes (warp-per-node, deep-unroll direct loads)
//          straight into the sA smem tile — no g_agg round trip.
// Phase 2: proven scalar quad-GRU (4 threads/node, 8 channels each).
__global__ void __launch_bounds__(128) k_gru(const float* __restrict__ lzw, const float* __restrict__ lrw,
                                             const float* __restrict__ lhw, const float* __restrict__ out_w,
                                             const float* __restrict__ out_b, float* __restrict__ out)
{
    __shared__ float sM[3 * 8 * 32];    // fused input projections (z,r,h)
    __shared__ float sW2[3 * 32 * 32];  // H-projections (z,r,h)
    __shared__ float sb[3 * 32];        // fused biases
    __shared__ float sOw[32 * TT];
    __shared__ float sOb[TT];
    __shared__ float sP[TT];
    __shared__ float sA[32 * 100];      // 32-node agg tile (pad 100)

    int tid = threadIdx.x;  // 128
    int wid = tid >> 5;
    int lane = tid & 31;
    int base = blockIdx.x * 32;

    // ---- weight staging (all threads) ----
    for (int i = tid; i < 768; i += 128) sM[i] = g_M[i];
    for (int i = tid; i < 1024; i += 128) {
        sW2[i]        = lzw[1024 + i];
        sW2[1024 + i] = lrw[1024 + i];
        sW2[2048 + i] = lhw[1024 + i];
    }
    for (int i = tid; i < 96; i += 128) sb[i] = g_gb[i];
    for (int i = tid; i < 32 * TT; i += 128) sOw[i] = out_w[i];
    if (tid < TT) { sOb[tid] = out_b[tid]; sP[tid] = g_probs[tid]; }

    // ---- phase 1: gather 8 nodes per warp into sA ----
#pragma unroll 1
    for (int ni = 0; ni < 8; ni++) {
        int nl = wid * 8 + ni;
        int n = base + nl;
        int beg = g_off[n], end = g_off[n + 1];
        float ds = g_dis[n];
        float nmself = ds * ds;  // self-loop norm = 1/deg
        const float* wn = g_wx + (size_t)n * FT;
        float a0 = nmself * wn[lane];
        float a1 = nmself * wn[lane + 32];
        float a2 = nmself * wn[lane + 64];
#pragma unroll 8
        for (int i = beg; i < end; i++) {
            u64 v = g_sSN[i];  // lane-uniform -> broadcast load
            int s = (int)(unsigned)(v & 0xffffffffu);
            float nm = __uint_as_float((unsigned)(v >> 32));
            const float* wr = g_wx + (size_t)s * FT;
            a0 += nm * wr[lane];
            a1 += nm * wr[lane + 32];
            a2 += nm * wr[lane + 64];
        }
        sA[nl * 100 + lane]      = a0;
        sA[nl * 100 + lane + 32] = a1;
        sA[nl * 100 + lane + 64] = a2;
    }
    __syncthreads();

    // ---- phase 2: GRU (4 threads/node) ----
    int q = lane & 3;           // quad slot -> channel block
    int c0 = q * 8;             // first owned channel
    int nl = tid >> 2;          // local node (0..31)
    int qbase = lane & ~3;
    const float* aRow = sA + nl * 100;

    float H[8], Ha[8];
#pragma unroll
    for (int j = 0; j < 8; j++) { H[j] = 0.f; Ha[j] = 0.f; }

#pragma unroll 1
    for (int t = 0; t < TT; t++) {
        float a[8];
#pragma unroll
        for (int f = 0; f < 8; f++) a[f] = aRow[f * TT + t];

        // ---- Z and R gates together (both use old H -> share shuffles) ----
        float z[8], r[8];
#pragma unroll
        for (int j = 0; j < 8; j++) { z[j] = sb[c0 + j]; r[j] = sb[32 + c0 + j]; }
#pragma unroll
        for (int f = 0; f < 8; f++) {
            float af = a[f];
#pragma unroll
            for (int j = 0; j < 8; j++) {
                z[j] += af * sM[f * 32 + c0 + j];
                r[j] += af * sM[256 + f * 32 + c0 + j];
            }
        }
#pragma unroll
        for (int k = 0; k < 32; k++) {
            float hk = __shfl_sync(0xffffffffu, H[k & 7], qbase | (k >> 3));
#pragma unroll
            for (int j = 0; j < 8; j++) {
                z[j] += hk * sW2[k * 32 + c0 + j];
                r[j] += hk * sW2[1024 + k * 32 + c0 + j];
            }
        }
#pragma unroll
        for (int j = 0; j < 8; j++) r[j] = sigf(r[j]) * H[j];  // r becomes H*R

        // ---- candidate gate (uses H*R) ----
        float hc[8];
#pragma unroll
        for (int j = 0; j < 8; j++) hc[j] = sb[64 + c0 + j];
#pragma unroll
        for (int f = 0; f < 8; f++) {
            float af = a[f];
#pragma unroll
            for (int j = 0; j < 8; j++) hc[j] += af * sM[512 + f * 32 + c0 + j];
        }
#pragma unroll
        for (int k = 0; k < 32; k++) {
            float hrk = __shfl_sync(0xffffffffu, r[k & 7], qbase | (k >> 3));
#pragma unroll
            for (int j = 0; j < 8; j++) hc[j] += hrk * sW2[2048 + k * 32 + c0 + j];
        }

        float pt = sP[t];
#pragma unroll
        for (int j = 0; j < 8; j++) {
            float zz = sigf(z[j]);
            float ht = tanhf(hc[j]);
            H[j] = zz * H[j] + (1.0f - zz) * ht;
            Ha[j] += pt * H[j];
        }
    }

    // ---- output head: relu(Ha) @ out_w + out_b, quad-reduced, smem-staged store ----
#pragma unroll
    for (int j = 0; j < 8; j++) Ha[j] = fmaxf(Ha[j], 0.f);
    float o[TT];
#pragma unroll
    for (int t = 0; t < TT; t++) {
        float acc = 0.f;
#pragma unroll
        for (int j = 0; j < 8; j++) acc += Ha[j] * sOw[(c0 + j) * TT + t];
        acc += __shfl_xor_sync(0xffffffffu, acc, 1);
        acc += __shfl_xor_sync(0xffffffffu, acc, 2);
        o[t] = acc + sOb[t];
    }
    __syncthreads();  // done reading sA -> reuse as output stage
    if (q == 0) {
#pragma unroll
        for (int t = 0; t < TT; t++) sA[nl * 13 + t] = o[t];
    }
    __syncthreads();
    for (int i = tid; i < 32 * TT; i += 128) {
        int row = i / TT, c = i % TT;
        out[(size_t)(base + row) * TT + c] = sA[row * 13 + c];
    }
}

// ---------------- launch ----------------
extern "C" void kernel_launch(void* const* d_in, const int* in_sizes, int n_in,
                              void* d_out, int out_size)
{
    const float* x     = (const float*)d_in[0];
    const int*   ei    = (const int*)d_in[1];
    const float* ew    = (const float*)d_in[2];
    const float* mlp_w = (const float*)d_in[3];
    const float* mlp_b = (const float*)d_in[4];
    const float* att   = (const float*)d_in[5];
    const float* czw   = (const float*)d_in[6];
    const float* czb   = (const float*)d_in[7];
    const float* lzw   = (const float*)d_in[8];
    const float* lzb   = (const float*)d_in[9];
    const float* crw   = (const float*)d_in[10];
    const float* crb   = (const float*)d_in[11];
    const float* lrw   = (const float*)d_in[12];
    const float* lrb   = (const float*)d_in[13];
    const float* chw   = (const float*)d_in[14];
    const float* chb   = (const float*)d_in[15];
    const float* lhw   = (const float*)d_in[16];
    const float* lhb   = (const float*)d_in[17];
    const float* ow    = (const float*)d_in[18];
    const float* ob    = (const float*)d_in[19];
    float* out = (float*)d_out;

    k_precompute<<<1, 256>>>(czw, czb, lzw, lzb, crw, crb, lrw, lrb, chw, chb, lhw, lhb, att);
    k_wx<<<(NN + 7) / 8, 256>>>(x, mlp_w, mlp_b);
    k_hist<<<(EE + 255) / 256, 256>>>(ei, ew);
    k_scan1<<<NB, 256>>>();
    k_scan2<<<1, 512>>>();
    k_scan3<<<NB, 256>>>();
    k_scatter<<<(EE + 255) / 256, 256>>>(ei, ew);
    k_gru<<<(NN + 31) / 32, 128>>>(lzw, lrw, lhw, ow, ob, out);
}

// round 16
// speedup vs baseline: 1.4383x; 1.1011x over previous
#include <cuda_runtime.h>

#define NN 100000
#define EE 1600000
#define FT 96
#define TT 12
#define NB 391  // ceil(NN/256)

typedef unsigned long long u64;

// ---------------- scratch (device globals; no runtime allocation) ----------------
__device__ float g_wx[(size_t)NN * FT];   // weighted features, node-major [n][j]
__device__ float g_agg[(size_t)NN * FT];  // aggregated features, node-major [n][j]
__device__ float g_dis[NN];
__device__ float g_wdeg[NN];
__device__ int   g_cnt[NN];
__device__ int   g_off[NN + 1];
__device__ int   g_cur[NN];
__device__ int   g_bsum[NB];
__device__ int   g_bpre[NB];
__device__ u64   g_sSN[EE];               // packed (src, norm) bucketed by dst
__device__ int   g_sD[EE];                // dst per sorted slot (for segmented reduce)
__device__ float g_M[3 * 8 * 32];
__device__ float g_gb[3 * 32];
__device__ float g_probs[TT];

__device__ __forceinline__ float sigf(float x) { return 1.0f / (1.0f + __expf(-x)); }

// ---------------- fused weight precompute + softmax(att) ----------------
__global__ void k_precompute(const float* czw, const float* czb, const float* lzw, const float* lzb,
                             const float* crw, const float* crb, const float* lrw, const float* lrb,
                             const float* chw, const float* chb, const float* lhw, const float* lhb,
                             const float* att)
{
    int tid = threadIdx.x;           // 256
    int f = tid >> 5, l = tid & 31;
#pragma unroll
    for (int g = 0; g < 3; g++) {
        const float* CW = (g == 0) ? czw : (g == 1) ? crw : chw;
        const float* CB = (g == 0) ? czb : (g == 1) ? crb : chb;
        const float* LW = (g == 0) ? lzw : (g == 1) ? lrw : lhw;
        const float* LB = (g == 0) ? lzb : (g == 1) ? lrb : lhb;
        float m = 0.f;
        for (int k = 0; k < 32; k++) m += CW[f * 32 + k] * LW[k * 32 + l];
        g_M[g * 256 + f * 32 + l] = m;
        if (f == 0) {
            float b = LB[l];
            for (int k = 0; k < 32; k++) b += CB[k] * LW[k * 32 + l];
            g_gb[g * 32 + l] = b;
        }
    }
    if (tid < TT) {
        float mx = -1e30f;
        for (int t = 0; t < TT; t++) mx = fmaxf(mx, att[t]);
        float s = 0.f;
        for (int t = 0; t < TT; t++) s += __expf(att[t] - mx);
        g_probs[tid] = __expf(att[tid] - mx) / s;
    }
}

// ---------------- wx = x * sigmoid(x_flat @ mlp_w + mlp_b); reset cnt/wdeg ----------------
__global__ void k_wx(const float* __restrict__ x, const float* __restrict__ mlp_w,
                     const float* __restrict__ mlp_b)
{
    __shared__ float sW[TT * FT];  // transposed: [t][j]
    __shared__ float sB[TT];
    int tid = threadIdx.x;  // 256
    for (int i = tid; i < TT * FT; i += 256) {
        int t = i / FT, j = i % FT;
        sW[i] = mlp_w[j * TT + t];
    }
    if (tid < TT) sB[tid] = mlp_b[tid];
    __syncthreads();

    int n = blockIdx.x * 8 + (tid >> 5);
    if (n >= NN) return;
    int lane = tid & 31;
    const float* xr = x + (size_t)n * FT;
    float x0 = xr[lane], x1 = xr[lane + 32], x2 = xr[lane + 64];

    float p[TT];
#pragma unroll
    for (int t = 0; t < TT; t++)
        p[t] = x0 * sW[t * FT + lane] + x1 * sW[t * FT + lane + 32] + x2 * sW[t * FT + lane + 64];
#pragma unroll
    for (int off = 16; off; off >>= 1) {
#pragma unroll
        for (int t = 0; t < TT; t++) p[t] += __shfl_xor_sync(0xffffffffu, p[t], off);
    }
    float* wr = g_wx + (size_t)n * FT;
    int j0 = lane % 12, j1 = (lane + 32) % 12, j2 = (lane + 64) % 12;
    wr[lane]      = x0 * sigf(p[j0] + sB[j0]);
    wr[lane + 32] = x1 * sigf(p[j1] + sB[j1]);
    wr[lane + 64] = x2 * sigf(p[j2] + sB[j2]);
    if (lane == 0) { g_cnt[n] = 0; g_wdeg[n] = 0.f; }  // replay-safe reset
}

// ---------------- histogram: in-edge count + weighted degree ----------------
__global__ void k_hist(const int* __restrict__ ei, const float* __restrict__ ew)
{
    int e = blockIdx.x * 256 + threadIdx.x;
    if (e < EE) {
        int d = ei[EE + e];
        atomicAdd(&g_cnt[d], 1);
        atomicAdd(&g_wdeg[d], ew[e]);
    }
}

// ---------------- scan stage 1 ----------------
__global__ void k_scan1()
{
    __shared__ int s[256];
    int t = threadIdx.x;
    int n = blockIdx.x * 256 + t;
    int v = (n < NN) ? g_cnt[n] : 0;
    s[t] = v; __syncthreads();
#pragma unroll
    for (int o = 128; o; o >>= 1) {
        if (t < o) s[t] += s[t + o];
        __syncthreads();
    }
    if (t == 0) g_bsum[blockIdx.x] = s[0];
}

// ---------------- scan stage 2 ----------------
__global__ void k_scan2()
{
    __shared__ int s[512];
    int t = threadIdx.x;  // 512
    int v = (t < NB) ? g_bsum[t] : 0;
    s[t] = v; __syncthreads();
#pragma unroll
    for (int o = 1; o < 512; o <<= 1) {
        int x = (t >= o) ? s[t - o] : 0;
        __syncthreads();
        s[t] += x;
        __syncthreads();
    }
    if (t < NB) g_bpre[t] = s[t] - v;
}

// ---------------- scan stage 3: offsets/cursors; dis = rsqrt(wdeg+1) ----------------
__global__ void k_scan3()
{
    __shared__ int s[256];
    int t = threadIdx.x;
    int n = blockIdx.x * 256 + t;
    int v = (n < NN) ? g_cnt[n] : 0;
    s[t] = v; __syncthreads();
#pragma unroll
    for (int o = 1; o < 256; o <<= 1) {
        int x = (t >= o) ? s[t - o] : 0;
        __syncthreads();
        s[t] += x;
        __syncthreads();
    }
    if (n < NN) {
        int off = g_bpre[blockIdx.x] + s[t] - v;
        g_off[n] = off;
        g_cur[n] = off;
        g_dis[n] = rsqrtf(g_wdeg[n] + 1.0f);
    }
    if (n == 0) g_off[NN] = EE;
}

// ---------------- self-loop init of agg (node-major, overwrite -> replay safe) ----------------
__global__ void k_selfinit()
{
    int n = blockIdx.x * 8 + (threadIdx.x >> 5);
    if (n >= NN) return;
    int lane = threadIdx.x & 31;
    float ds = g_dis[n];
    float inv = ds * ds;  // self-loop norm = 1/deg
    const float* wr = g_wx + (size_t)n * FT;
    float* ar = g_agg + (size_t)n * FT;
#pragma unroll
    for (int q = 0; q < 3; q++) {
        int j = lane + 32 * q;
        ar[j] = wr[j] * inv;
    }
}

// ---------------- scatter edges into dst-buckets: (src,norm) + dst ----------------
__global__ void k_scatter(const int* __restrict__ ei, const float* __restrict__ ew)
{
    int e = blockIdx.x * 256 + threadIdx.x;
    if (e >= EE) return;
    int s = ei[e], d = ei[EE + e];
    float nm = g_dis[s] * ew[e] * g_dis[d];
    int p = atomicAdd(&g_cur[d], 1);
    g_sSN[p] = ((u64)(unsigned)s) | ((u64)__float_as_uint(nm) << 32);
    g_sD[p] = d;
}

// ---------------- edge-parallel segmented reduction: warp per 32-edge chunk ----------------
// EE/32 = 50000 chunks exactly — perfect balance, no per-node latency chains.
// Partial sums in registers; atomic flush only at dst boundaries (~2 per chunk).
__global__ void k_edgesum()
{
    int w = blockIdx.x * 8 + (threadIdx.x >> 5);  // chunk id, 50000 total
    int lane = threadIdx.x & 31;
    int e = w * 32 + lane;
    u64 v = g_sSN[e];          // coalesced LDG.64
    int dd = g_sD[e];          // coalesced LDG.32
    unsigned vlo = (unsigned)(v & 0xffffffffu);
    unsigned vhi = (unsigned)(v >> 32);

    float a0 = 0.f, a1 = 0.f, a2 = 0.f;
    int dcur = __shfl_sync(0xffffffffu, dd, 0);
#pragma unroll
    for (int i = 0; i < 32; i++) {
        int di = __shfl_sync(0xffffffffu, dd, i);       // warp-uniform
        if (di != dcur) {                                // uniform branch
            float* ar = g_agg + (size_t)dcur * FT;
            atomicAdd(ar + lane, a0);
            atomicAdd(ar + lane + 32, a1);
            atomicAdd(ar + lane + 64, a2);
            a0 = a1 = a2 = 0.f;
            dcur = di;
        }
        int s = (int)__shfl_sync(0xffffffffu, vlo, i);
        float nm = __uint_as_float(__shfl_sync(0xffffffffu, vhi, i));
        const float* wr = g_wx + (size_t)s * FT;
        a0 += nm * wr[lane];
        a1 += nm * wr[lane + 32];
        a2 += nm * wr[lane + 64];
    }
    float* ar = g_agg + (size_t)dcur * FT;
    atomicAdd(ar + lane, a0);
    atomicAdd(ar + lane + 32, a1);
    atomicAdd(ar + lane + 64, a2);
}

// ---------------- per-node GRU recurrence + output head (proven R9 version) ----------------
__global__ void __launch_bounds__(128) k_gru(const float* __restrict__ lzw, const float* __restrict__ lrw,
                                             const float* __restrict__ lhw, const float* __restrict__ out_w,
                                             const float* __restrict__ out_b, float* __restrict__ out)
{
    __shared__ float sM[3 * 8 * 32];    // fused input projections (z,r,h)
    __shared__ float sW2[3 * 32 * 32];  // H-projections (z,r,h)
    __shared__ float sb[3 * 32];        // fused biases
    __shared__ float sOw[32 * TT];
    __shared__ float sOb[TT];
    __shared__ float sP[TT];
    __shared__ float sA[32 * 100];      // 32-node agg tile (pad 100)

    int tid = threadIdx.x;  // 128
    for (int i = tid; i < 768; i += 128) sM[i] = g_M[i];
    for (int i = tid; i < 1024; i += 128) {
        sW2[i]        = lzw[1024 + i];
        sW2[1024 + i] = lrw[1024 + i];
        sW2[2048 + i] = lhw[1024 + i];
    }
    for (int i = tid; i < 96; i += 128) sb[i] = g_gb[i];
    for (int i = tid; i < 32 * TT; i += 128) sOw[i] = out_w[i];
    if (tid < TT) { sOb[tid] = out_b[tid]; sP[tid] = g_probs[tid]; }

    int base = blockIdx.x * 32;
    for (int i = tid; i < 32 * FT; i += 128) {
        int nl = i / FT, j = i % FT;
        sA[nl * 100 + j] = g_agg[(size_t)(base + nl) * FT + j];
    }
    __syncthreads();

    int lane = tid & 31;
    int q = lane & 3;           // quad slot -> channel block
    int c0 = q * 8;             // first owned channel
    int nl = tid >> 2;          // local node (0..31)
    int qbase = lane & ~3;
    const float* aRow = sA + nl * 100;

    float H[8], Ha[8];
#pragma unroll
    for (int j = 0; j < 8; j++) { H[j] = 0.f; Ha[j] = 0.f; }

#pragma unroll 1
    for (int t = 0; t < TT; t++) {
        float a[8];
#pragma unroll
        for (int f = 0; f < 8; f++) a[f] = aRow[f * TT + t];

        // ---- Z and R gates together (both use old H -> share shuffles) ----
        float z[8], r[8];
#pragma unroll
        for (int j = 0; j < 8; j++) { z[j] = sb[c0 + j]; r[j] = sb[32 + c0 + j]; }
#pragma unroll
        for (int f = 0; f < 8; f++) {
            float af = a[f];
#pragma unroll
            for (int j = 0; j < 8; j++) {
                z[j] += af * sM[f * 32 + c0 + j];
                r[j] += af * sM[256 + f * 32 + c0 + j];
            }
        }
#pragma unroll
        for (int k = 0; k < 32; k++) {
            float hk = __shfl_sync(0xffffffffu, H[k & 7], qbase | (k >> 3));
#pragma unroll
            for (int j = 0; j < 8; j++) {
                z[j] += hk * sW2[k * 32 + c0 + j];
                r[j] += hk * sW2[1024 + k * 32 + c0 + j];
            }
        }
#pragma unroll
        for (int j = 0; j < 8; j++) r[j] = sigf(r[j]) * H[j];  // r becomes H*R

        // ---- candidate gate (uses H*R) ----
        float hc[8];
#pragma unroll
        for (int j = 0; j < 8; j++) hc[j] = sb[64 + c0 + j];
#pragma unroll
        for (int f = 0; f < 8; f++) {
            float af = a[f];
#pragma unroll
            for (int j = 0; j < 8; j++) hc[j] += af * sM[512 + f * 32 + c0 + j];
        }
#pragma unroll
        for (int k = 0; k < 32; k++) {
            float hrk = __shfl_sync(0xffffffffu, r[k & 7], qbase | (k >> 3));
#pragma unroll
            for (int j = 0; j < 8; j++) hc[j] += hrk * sW2[2048 + k * 32 + c0 + j];
        }

        float pt = sP[t];
#pragma unroll
        for (int j = 0; j < 8; j++) {
            float zz = sigf(z[j]);
            float ht = tanhf(hc[j]);
            H[j] = zz * H[j] + (1.0f - zz) * ht;
            Ha[j] += pt * H[j];
        }
    }

    // ---- output head: relu(Ha) @ out_w + out_b, quad-reduced, smem-staged store ----
#pragma unroll
    for (int j = 0; j < 8; j++) Ha[j] = fmaxf(Ha[j], 0.f);
    float o[TT];
#pragma unroll
    for (int t = 0; t < TT; t++) {
        float acc = 0.f;
#pragma unroll
        for (int j = 0; j < 8; j++) acc += Ha[j] * sOw[(c0 + j) * TT + t];
        acc += __shfl_xor_sync(0xffffffffu, acc, 1);
        acc += __shfl_xor_sync(0xffffffffu, acc, 2);
        o[t] = acc + sOb[t];
    }
    __syncthreads();  // done reading sA -> reuse as output stage
    if (q == 0) {
#pragma unroll
        for (int t = 0; t < TT; t++) sA[nl * 13 + t] = o[t];
    }
    __syncthreads();
    for (int i = tid; i < 32 * TT; i += 128) {
        int row = i / TT, c = i % TT;
        out[(size_t)(base + row) * TT + c] = sA[row * 13 + c];
    }
}

// ---------------- launch ----------------
extern "C" void kernel_launch(void* const* d_in, const int* in_sizes, int n_in,
                              void* d_out, int out_size)
{
    const float* x     = (const float*)d_in[0];
    const int*   ei    = (const int*)d_in[1];
    const float* ew    = (const float*)d_in[2];
    const float* mlp_w = (const float*)d_in[3];
    const float* mlp_b = (const float*)d_in[4];
    const float* att   = (const float*)d_in[5];
    const float* czw   = (const float*)d_in[6];
    const float* czb   = (const float*)d_in[7];
    const float* lzw   = (const float*)d_in[8];
    const float* lzb   = (const float*)d_in[9];
    const float* crw   = (const float*)d_in[10];
    const float* crb   = (const float*)d_in[11];
    const float* lrw   = (const float*)d_in[12];
    const float* lrb   = (const float*)d_in[13];
    const float* chw   = (const float*)d_in[14];
    const float* chb   = (const float*)d_in[15];
    const float* lhw   = (const float*)d_in[16];
    const float* lhb   = (const float*)d_in[17];
    const float* ow    = (const float*)d_in[18];
    const float* ob    = (const float*)d_in[19];
    float* out = (float*)d_out;

    k_precompute<<<1, 256>>>(czw, czb, lzw, lzb, crw, crb, lrw, lrb, chw, chb, lhw, lhb, att);
    k_wx<<<(NN + 7) / 8, 256>>>(x, mlp_w, mlp_b);
    k_hist<<<(EE + 255) / 256, 256>>>(ei, ew);
    k_scan1<<<NB, 256>>>();
    k_scan2<<<1, 512>>>();
    k_scan3<<<NB, 256>>>();
    k_selfinit<<<(NN + 7) / 8, 256>>>();
    k_scatter<<<(EE + 255) / 256, 256>>>(ei, ew);
    k_edgesum<<<EE / 32 / 8, 256>>>();
    k_gru<<<(NN * 4) / 128, 128>>>(lzw, lrw, lhw, ow, ob, out);
}

// round 17
// speedup vs baseline: 1.4414x; 1.0022x over previous
#include <cuda_runtime.h>

#define NN 100000
#define EE 1600000
#define FT 96
#define TT 12
#define NB 391  // ceil(NN/256)

typedef unsigned long long u64;

// ---------------- scratch (device globals; no runtime allocation) ----------------
__device__ float g_wx[(size_t)NN * FT];   // weighted features, node-major [n][j]
__device__ float g_agg[(size_t)NN * FT];  // aggregated features, node-major [n][j]
__device__ float g_dis[NN];
__device__ float g_wdeg[NN];              // zeroed after use in scan23
__device__ int   g_cnt[NN];               // zeroed after use in scan23
__device__ int   g_off[NN + 1];
__device__ int   g_cur[NN];
__device__ int   g_bsum[NB];
__device__ u64   g_sSN[EE];               // packed (src, norm) bucketed by dst
__device__ float g_M[3 * 8 * 32];
__device__ float g_gb[3 * 32];
__device__ float g_probs[TT];

__device__ __forceinline__ float sigf(float x) { return 1.0f / (1.0f + __expf(-x)); }

// ---------------- fused weight precompute + softmax(att) ----------------
__global__ void k_precompute(const float* czw, const float* czb, const float* lzw, const float* lzb,
                             const float* crw, const float* crb, const float* lrw, const float* lrb,
                             const float* chw, const float* chb, const float* lhw, const float* lhb,
                             const float* att)
{
    int tid = threadIdx.x;           // 256
    int f = tid >> 5, l = tid & 31;
#pragma unroll
    for (int g = 0; g < 3; g++) {
        const float* CW = (g == 0) ? czw : (g == 1) ? crw : chw;
        const float* CB = (g == 0) ? czb : (g == 1) ? crb : chb;
        const float* LW = (g == 0) ? lzw : (g == 1) ? lrw : lhw;
        const float* LB = (g == 0) ? lzb : (g == 1) ? lrb : lhb;
        float m = 0.f;
        for (int k = 0; k < 32; k++) m += CW[f * 32 + k] * LW[k * 32 + l];
        g_M[g * 256 + f * 32 + l] = m;
        if (f == 0) {
            float b = LB[l];
            for (int k = 0; k < 32; k++) b += CB[k] * LW[k * 32 + l];
            g_gb[g * 32 + l] = b;
        }
    }
    if (tid < TT) {
        float mx = -1e30f;
        for (int t = 0; t < TT; t++) mx = fmaxf(mx, att[t]);
        float s = 0.f;
        for (int t = 0; t < TT; t++) s += __expf(att[t] - mx);
        g_probs[tid] = __expf(att[tid] - mx) / s;
    }
}

// ---------------- wx = x * sigmoid(x_flat @ mlp_w + mlp_b) ----------------
__global__ void k_wx(const float* __restrict__ x, const float* __restrict__ mlp_w,
                     const float* __restrict__ mlp_b)
{
    __shared__ float sW[TT * FT];  // transposed: [t][j]
    __shared__ float sB[TT];
    int tid = threadIdx.x;  // 256
    for (int i = tid; i < TT * FT; i += 256) {
        int t = i / FT, j = i % FT;
        sW[i] = mlp_w[j * TT + t];
    }
    if (tid < TT) sB[tid] = mlp_b[tid];
    __syncthreads();

    int n = blockIdx.x * 8 + (tid >> 5);
    if (n >= NN) return;
    int lane = tid & 31;
    const float* xr = x + (size_t)n * FT;
    float x0 = xr[lane], x1 = xr[lane + 32], x2 = xr[lane + 64];

    float p[TT];
#pragma unroll
    for (int t = 0; t < TT; t++)
        p[t] = x0 * sW[t * FT + lane] + x1 * sW[t * FT + lane + 32] + x2 * sW[t * FT + lane + 64];
#pragma unroll
    for (int off = 16; off; off >>= 1) {
#pragma unroll
        for (int t = 0; t < TT; t++) p[t] += __shfl_xor_sync(0xffffffffu, p[t], off);
    }
    float* wr = g_wx + (size_t)n * FT;
    int j0 = lane % 12, j1 = (lane + 32) % 12, j2 = (lane + 64) % 12;
    wr[lane]      = x0 * sigf(p[j0] + sB[j0]);
    wr[lane + 32] = x1 * sigf(p[j1] + sB[j1]);
    wr[lane + 64] = x2 * sigf(p[j2] + sB[j2]);
}

// ---------------- histogram: in-edge count + weighted degree ----------------
// cnt/wdeg are zero at entry: zero-initialized on first call, zeroed by scan23 afterwards.
__global__ void k_hist(const int* __restrict__ ei, const float* __restrict__ ew)
{
    int e = blockIdx.x * 256 + threadIdx.x;
    if (e < EE) {
        int d = ei[EE + e];
        atomicAdd(&g_cnt[d], 1);
        atomicAdd(&g_wdeg[d], ew[e]);
    }
}

// ---------------- scan stage 1: per-block sums of cnt ----------------
__global__ void k_scan1()
{
    __shared__ int s[256];
    int t = threadIdx.x;
    int n = blockIdx.x * 256 + t;
    int v = (n < NN) ? g_cnt[n] : 0;
    s[t] = v; __syncthreads();
#pragma unroll
    for (int o = 128; o; o >>= 1) {
        if (t < o) s[t] += s[t + o];
        __syncthreads();
    }
    if (t == 0) g_bsum[blockIdx.x] = s[0];
}

// ---------------- scan 2+3 merged: offsets/cursors; dis; reset cnt/wdeg ----------------
// Each block warp-scans all NB block sums itself (correctness proven in R11).
__global__ void k_scan23()
{
    __shared__ int s[256];
    __shared__ int sbp;  // this block's exclusive prefix
    int t = threadIdx.x;
    int lane = t & 31;

    if (t < 32) {
        int carry = 0;
        int myb = blockIdx.x;
        for (int c = 0; c < NB; c += 32) {
            int i = c + lane;
            int v = (i < NB) ? g_bsum[i] : 0;
            int x = v;  // inclusive warp scan
#pragma unroll
            for (int o = 1; o < 32; o <<= 1) {
                int y = __shfl_up_sync(0xffffffffu, x, o);
                if (lane >= o) x += y;
            }
            int total = __shfl_sync(0xffffffffu, x, 31);
            if (i == myb) sbp = carry + x - v;  // exclusive
            carry += total;
        }
    }

    int n = blockIdx.x * 256 + t;
    int v = (n < NN) ? g_cnt[n] : 0;
    s[t] = v; __syncthreads();  // also publishes sbp
#pragma unroll
    for (int o = 1; o < 256; o <<= 1) {
        int x = (t >= o) ? s[t - o] : 0;
        __syncthreads();
        s[t] += x;
        __syncthreads();
    }
    if (n < NN) {
        int off = sbp + s[t] - v;
        g_off[n] = off;
        g_cur[n] = off;
        g_dis[n] = rsqrtf(g_wdeg[n] + 1.0f);
        g_cnt[n] = 0;     // zero-after-use: ready for next graph replay
        g_wdeg[n] = 0.f;
    }
    if (n == 0) g_off[NN] = EE;
}

// ---------------- scatter edges into dst-buckets: packed (src, norm) ----------------
__global__ void k_scatter(const int* __restrict__ ei, const float* __restrict__ ew)
{
    int e = blockIdx.x * 256 + threadIdx.x;
    if (e >= EE) return;
    int s = ei[e], d = ei[EE + e];
    float nm = g_dis[s] * ew[e] * g_dis[d];
    int p = atomicAdd(&g_cur[d], 1);
    g_sSN[p] = ((u64)(unsigned)s) | ((u64)__float_as_uint(nm) << 32);
}

// ---------------- gather: agg[n] = self + sum in-edges (exact R9 version) ----------------
__global__ void k_gather()
{
    int n = blockIdx.x * 8 + (threadIdx.x >> 5);
    if (n >= NN) return;
    int lane = threadIdx.x & 31;
    int beg = g_off[n], end = g_off[n + 1];
    float ds = g_dis[n];
    float nmself = ds * ds;  // self-loop norm = 1/deg
    const float* wn = g_wx + (size_t)n * FT;
    float a0 = nmself * wn[lane];
    float a1 = nmself * wn[lane + 32];
    float a2 = nmself * wn[lane + 64];

    for (int b = beg; b < end; b += 32) {
        int m = end - b; if (m > 32) m = 32;
        u64 v = (b + lane < end) ? g_sSN[b + lane] : 0ull;  // coalesced LDG.64
        unsigned vlo = (unsigned)(v & 0xffffffffu);
        unsigned vhi = (unsigned)(v >> 32);
#pragma unroll 4
        for (int i = 0; i < m; i++) {
            int s = (int)__shfl_sync(0xffffffffu, vlo, i);
            float nm = __uint_as_float(__shfl_sync(0xffffffffu, vhi, i));
            const float* wr = g_wx + (size_t)s * FT;
            a0 += nm * wr[lane];
            a1 += nm * wr[lane + 32];
            a2 += nm * wr[lane + 64];
        }
    }
    float* ar = g_agg + (size_t)n * FT;
    ar[lane] = a0; ar[lane + 32] = a1; ar[lane + 64] = a2;
}

// ---------------- per-node GRU + output head: 256 threads, 64 nodes per block ----------------
// Same proven quad-GRU inner code; bigger block halves weight-staging traffic
// and raises warps/SM. Tail block (last 32 nodes) guarded via zero-padded sA.
__global__ void __launch_bounds__(256) k_gru(const float* __restrict__ lzw, const float* __restrict__ lrw,
                                             const float* __restrict__ lhw, const float* __restrict__ out_w,
                                             const float* __restrict__ out_b, float* __restrict__ out)
{
    __shared__ float sM[3 * 8 * 32];    // fused input projections (z,r,h)
    __shared__ float sW2[3 * 32 * 32];  // H-projections (z,r,h)
    __shared__ float sb[3 * 32];        // fused biases
    __shared__ float sOw[32 * TT];
    __shared__ float sOb[TT];
    __shared__ float sP[TT];
    __shared__ float sA[64 * 100];      // 64-node agg tile (pad 100)

    int tid = threadIdx.x;  // 256
    for (int i = tid; i < 768; i += 256) sM[i] = g_M[i];
    for (int i = tid; i < 1024; i += 256) {
        sW2[i]        = lzw[1024 + i];
        sW2[1024 + i] = lrw[1024 + i];
        sW2[2048 + i] = lhw[1024 + i];
    }
    for (int i = tid; i < 96; i += 256) sb[i] = g_gb[i];
    for (int i = tid; i < 32 * TT; i += 256) sOw[i] = out_w[i];
    if (tid < TT) { sOb[tid] = out_b[tid]; sP[tid] = g_probs[tid]; }

    int base = blockIdx.x * 64;
    for (int i = tid; i < 64 * FT; i += 256) {
        int nl = i / FT, j = i % FT;
        int gn = base + nl;
        sA[nl * 100 + j] = (gn < NN) ? g_agg[(size_t)gn * FT + j] : 0.f;
    }
    __syncthreads();

    int lane = tid & 31;
    int q = lane & 3;           // quad slot -> channel block
    int c0 = q * 8;             // first owned channel
    int nl = tid >> 2;          // local node (0..63)
    int qbase = lane & ~3;
    const float* aRow = sA + nl * 100;

    float H[8], Ha[8];
#pragma unroll
    for (int j = 0; j < 8; j++) { H[j] = 0.f; Ha[j] = 0.f; }

#pragma unroll 1
    for (int t = 0; t < TT; t++) {
        float a[8];
#pragma unroll
        for (int f = 0; f < 8; f++) a[f] = aRow[f * TT + t];

        // ---- Z and R gates together (both use old H -> share shuffles) ----
        float z[8], r[8];
#pragma unroll
        for (int j = 0; j < 8; j++) { z[j] = sb[c0 + j]; r[j] = sb[32 + c0 + j]; }
#pragma unroll
        for (int f = 0; f < 8; f++) {
            float af = a[f];
#pragma unroll
            for (int j = 0; j < 8; j++) {
                z[j] += af * sM[f * 32 + c0 + j];
                r[j] += af * sM[256 + f * 32 + c0 + j];
            }
        }
#pragma unroll
        for (int k = 0; k < 32; k++) {
            float hk = __shfl_sync(0xffffffffu, H[k & 7], qbase | (k >> 3));
#pragma unroll
            for (int j = 0; j < 8; j++) {
                z[j] += hk * sW2[k * 32 + c0 + j];
                r[j] += hk * sW2[1024 + k * 32 + c0 + j];
            }
        }
#pragma unroll
        for (int j = 0; j < 8; j++) r[j] = sigf(r[j]) * H[j];  // r becomes H*R

        // ---- candidate gate (uses H*R) ----
        float hc[8];
#pragma unroll
        for (int j = 0; j < 8; j++) hc[j] = sb[64 + c0 + j];
#pragma unroll
        for (int f = 0; f < 8; f++) {
            float af = a[f];
#pragma unroll
            for (int j = 0; j < 8; j++) hc[j] += af * sM[512 + f * 32 + c0 + j];
        }
#pragma unroll
        for (int k = 0; k < 32; k++) {
            float hrk = __shfl_sync(0xffffffffu, r[k & 7], qbase | (k >> 3));
#pragma unroll
            for (int j = 0; j < 8; j++) hc[j] += hrk * sW2[2048 + k * 32 + c0 + j];
        }

        float pt = sP[t];
#pragma unroll
        for (int j = 0; j < 8; j++) {
            float zz = sigf(z[j]);
            float ht = tanhf(hc[j]);
            H[j] = zz * H[j] + (1.0f - zz) * ht;
            Ha[j] += pt * H[j];
        }
    }

    // ---- output head: relu(Ha) @ out_w + out_b, quad-reduced, smem-staged store ----
#pragma unroll
    for (int j = 0; j < 8; j++) Ha[j] = fmaxf(Ha[j], 0.f);
    float o[TT];
#pragma unroll
    for (int t = 0; t < TT; t++) {
        float acc = 0.f;
#pragma unroll
        for (int j = 0; j < 8; j++) acc += Ha[j] * sOw[(c0 + j) * TT + t];
        acc += __shfl_xor_sync(0xffffffffu, acc, 1);
        acc += __shfl_xor_sync(0xffffffffu, acc, 2);
        o[t] = acc + sOb[t];
    }
    __syncthreads();  // done reading sA -> reuse as output stage
    if (q == 0) {
#pragma unroll
        for (int t = 0; t < TT; t++) sA[nl * 13 + t] = o[t];
    }
    __syncthreads();
    for (int i = tid; i < 64 * TT; i += 256) {
        int row = i / TT, c = i % TT;
        int gn = base + row;
        if (gn < NN) out[(size_t)gn * TT + c] = sA[row * 13 + c];
    }
}

// ---------------- launch ----------------
extern "C" void kernel_launch(void* const* d_in, const int* in_sizes, int n_in,
                              void* d_out, int out_size)
{
    const float* x     = (const float*)d_in[0];
    const int*   ei    = (const int*)d_in[1];
    const float* ew    = (const float*)d_in[2];
    const float* mlp_w = (const float*)d_in[3];
    const float* mlp_b = (const float*)d_in[4];
    const float* att   = (const float*)d_in[5];
    const float* czw   = (const float*)d_in[6];
    const float* czb   = (const float*)d_in[7];
    const float* lzw   = (const float*)d_in[8];
    const float* lzb   = (const float*)d_in[9];
    const float* crw   = (const float*)d_in[10];
    const float* crb   = (const float*)d_in[11];
    const float* lrw   = (const float*)d_in[12];
    const float* lrb   = (const float*)d_in[13];
    const float* chw   = (const float*)d_in[14];
    const float* chb   = (const float*)d_in[15];
    const float* lhw   = (const float*)d_in[16];
    const float* lhb   = (const float*)d_in[17];
    const float* ow    = (const float*)d_in[18];
    const float* ob    = (const float*)d_in[19];
    float* out = (float*)d_out;

    k_precompute<<<1, 256>>>(czw, czb, lzw, lzb, crw, crb, lrw, lrb, chw, chb, lhw, lhb, att);
    k_wx<<<(NN + 7) / 8, 256>>>(x, mlp_w, mlp_b);
    k_hist<<<(EE + 255) / 256, 256>>>(ei, ew);
    k_scan1<<<NB, 256>>>();
    k_scan23<<<NB, 256>>>();
    k_scatter<<<(EE + 255) / 256, 256>>>(ei, ew);
    k_gather<<<(NN + 7) / 8, 256>>>();
    k_gru<<<(NN + 63) / 64, 256>>>(lzw, lrw, lhw, ow, ob, out);
}